// round 7
// baseline (speedup 1.0000x reference)
#include <cuda_runtime.h>
#include <cuda_bf16.h>
#include <cstdint>
#include <cstddef>

#define BATCH 32
#define TT    1024
#define II    512
#define HH    512
#define G3    1536
#define NCTA_PER_DIR 32

// ---------------- device scratch ----------------
__device__ float d_xn[(size_t)BATCH * TT * II];
__device__ float d_xp[(size_t)2 * TT * G3 * BATCH];
__device__ float d_wihr[2 * G3 * II];
__device__ float d_whpf[2 * NCTA_PER_DIR * 64 * 384];
__device__ float d_h[2 * 4 * 16384];                    // h 4-deep ring [dir][buf][16384]
__device__ unsigned int d_f1[2 * 32 * 32];              // produce flags, 128B padded
__device__ unsigned int d_f2[2 * 32 * 32];              // consume flags, 128B padded

// ---------------- helpers ----------------
__device__ __forceinline__ float tf32r(float x) {
    uint32_t u; asm("cvt.rna.tf32.f32 %0, %1;" : "=r"(u) : "f"(x));
    return __uint_as_float(u);
}
__device__ __forceinline__ void cp16(void* smem_dst, const void* gmem_src) {
    uint32_t s = (uint32_t)__cvta_generic_to_shared(smem_dst);
    asm volatile("cp.async.cg.shared.global [%0], [%1], 16;" :: "r"(s), "l"(gmem_src));
}
__device__ __forceinline__ void cp_commit() { asm volatile("cp.async.commit_group;"); }
template <int N> __device__ __forceinline__ void cp_wait() {
    asm volatile("cp.async.wait_group %0;" :: "n"(N));
}
__device__ __forceinline__ unsigned ldacq(const unsigned* p) {
    unsigned v; asm volatile("ld.acquire.gpu.global.u32 %0, [%1];" : "=r"(v) : "l"(p)); return v;
}
__device__ __forceinline__ unsigned ldrlx(const unsigned* p) {
    unsigned v; asm volatile("ld.relaxed.gpu.global.u32 %0, [%1];" : "=r"(v) : "l"(p)); return v;
}
__device__ __forceinline__ void strlx(unsigned* p, unsigned v) {
    asm volatile("st.relaxed.gpu.global.u32 [%0], %1;" :: "l"(p), "r"(v));
}
__device__ __forceinline__ void mma_tf32(float* d, const uint32_t* a, const uint32_t* b) {
    asm volatile(
        "mma.sync.aligned.m16n8k8.row.col.f32.tf32.tf32.f32 "
        "{%0,%1,%2,%3},{%4,%5,%6,%7},{%8,%9},{%0,%1,%2,%3};"
        : "+f"(d[0]), "+f"(d[1]), "+f"(d[2]), "+f"(d[3])
        : "r"(a[0]), "r"(a[1]), "r"(a[2]), "r"(a[3]), "r"(b[0]), "r"(b[1]));
}
__device__ __forceinline__ void mma_tf32_f(float* d, const float4& a, const float2& b) {
    asm volatile(
        "mma.sync.aligned.m16n8k8.row.col.f32.tf32.tf32.f32 "
        "{%0,%1,%2,%3},{%4,%5,%6,%7},{%8,%9},{%0,%1,%2,%3};"
        : "+f"(d[0]), "+f"(d[1]), "+f"(d[2]), "+f"(d[3])
        : "r"(__float_as_uint(a.x)), "r"(__float_as_uint(a.y)),
          "r"(__float_as_uint(a.z)), "r"(__float_as_uint(a.w)),
          "r"(__float_as_uint(b.x)), "r"(__float_as_uint(b.y)));
}
__device__ __forceinline__ int gate_row(int c, int j) {
    return (j < 16) ? (c * 16 + j)
         : (j < 32) ? (512 + c * 16 + (j - 16))
                    : (1024 + c * 16 + (j - 32));
}

// ---------------- kernel 0: prep ----------------
__global__ void prep_kernel(const float* __restrict__ wihf, const float* __restrict__ whhf,
                            const float* __restrict__ wihb, const float* __restrict__ whhb) {
    int idx = blockIdx.x * blockDim.x + threadIdx.x;
    int stride = gridDim.x * blockDim.x;
    for (int i = idx; i < 2 * G3 * II; i += stride) {
        int dir = i / (G3 * II);
        int r = i - dir * (G3 * II);
        d_wihr[i] = tf32r((dir ? wihb : wihf)[r]);
    }
    for (int i = idx; i < 2 * NCTA_PER_DIR * 64 * 384; i += stride) {
        int reg  = i & 3;
        int lane = (i >> 2) & 31;
        int mi   = (i % 384) / 128;
        int kk   = (i / 384) & 63;
        int c    = (i / (384 * 64)) % NCTA_PER_DIR;
        int dir  = i / (384 * 64 * NCTA_PER_DIR);
        int j = mi * 16 + (lane >> 2) + 8 * (reg & 1);
        int k = kk * 8 + (lane & 3) + 4 * (reg >> 1);
        const float* w = dir ? whhb : whhf;
        d_whpf[i] = tf32r(w[gate_row(c, j) * II + k]);
    }
    for (int i = idx; i < 2 * 4 * 16384; i += stride) d_h[i] = 0.0f;
    for (int i = idx; i < 2 * 32 * 32; i += stride) { d_f1[i] = 0u; d_f2[i] = 0u; }
}

// ---------------- kernel 1: LayerNorm ----------------
__global__ void ln_kernel(const float* __restrict__ x, const float* __restrict__ gamma,
                          const float* __restrict__ beta) {
    int row = blockIdx.x;
    const float* xr = x + (size_t)row * II;
    int tid = threadIdx.x;
    float v[4]; float s = 0.f, q = 0.f;
#pragma unroll
    for (int k = 0; k < 4; k++) {
        v[k] = xr[tid + 128 * k];
        s += v[k]; q += v[k] * v[k];
    }
#pragma unroll
    for (int o = 16; o > 0; o >>= 1) {
        s += __shfl_xor_sync(0xffffffffu, s, o);
        q += __shfl_xor_sync(0xffffffffu, q, o);
    }
    __shared__ float ws[4], wq[4];
    if ((tid & 31) == 0) { ws[tid >> 5] = s; wq[tid >> 5] = q; }
    __syncthreads();
    s = ws[0] + ws[1] + ws[2] + ws[3];
    q = wq[0] + wq[1] + wq[2] + wq[3];
    float mu = s * (1.0f / 512.0f);
    float var = q * (1.0f / 512.0f) - mu * mu;
    float rstd = rsqrtf(var + 1e-5f);
#pragma unroll
    for (int k = 0; k < 4; k++) {
        int i = tid + 128 * k;
        d_xn[(size_t)row * II + i] = tf32r((v[k] - mu) * rstd * gamma[i] + beta[i]);
    }
}

// ---------------- kernel 2: input-projection GEMM ----------------
#define GEMM_BUF_FLOATS (128 * 36)
__global__ void __launch_bounds__(256)
gemm_kernel(const float* __restrict__ bihf, const float* __restrict__ bihb) {
    extern __shared__ float smem[];
    float* As = smem;
    float* Bs = smem + 2 * GEMM_BUF_FLOATS;
    int bx = blockIdx.x, by = blockIdx.y, dir = blockIdx.z;
    int tid = threadIdx.x, lane = tid & 31, wid = tid >> 5;
    int wm = wid & 1, wn = wid >> 1;
    const float* bih = dir ? bihb : bihf;
    const float* Abase = d_wihr + (size_t)dir * G3 * II + (size_t)(by * 128) * II;

    auto load_tiles = [&](int kb, int buf) {
        float* As_ = As + buf * GEMM_BUF_FLOATS;
        float* Bs_ = Bs + buf * GEMM_BUF_FLOATS;
#pragma unroll
        for (int u = 0; u < 4; u++) {
            int o = tid + 256 * u;
            int row = o >> 3, seg = o & 7;
            cp16(&As_[row * 36 + seg * 4], Abase + (size_t)row * II + kb * 32 + seg * 4);
        }
#pragma unroll
        for (int u = 0; u < 4; u++) {
            int o = tid + 256 * u;
            int col = o >> 3, seg = o & 7;
            int n = bx * 128 + col;
            int t = n >> 5, b = n & 31;
            cp16(&Bs_[col * 36 + seg * 4], d_xn + ((size_t)b * TT + t) * II + kb * 32 + seg * 4);
        }
    };

    float acc[4][4][4];
#pragma unroll
    for (int i = 0; i < 4; i++)
#pragma unroll
        for (int j = 0; j < 4; j++)
#pragma unroll
            for (int k = 0; k < 4; k++) acc[i][j][k] = 0.f;

    load_tiles(0, 0); cp_commit();
    for (int kb = 0; kb < 16; kb++) {
        if (kb + 1 < 16) { load_tiles(kb + 1, (kb + 1) & 1); cp_commit(); cp_wait<1>(); }
        else cp_wait<0>();
        __syncthreads();
        float* As_ = As + (kb & 1) * GEMM_BUF_FLOATS;
        float* Bs_ = Bs + (kb & 1) * GEMM_BUF_FLOATS;
#pragma unroll
        for (int ks = 0; ks < 4; ks++) {
            int k0 = ks * 8 + (lane & 3);
            uint32_t af[4][4], bf[4][2];
#pragma unroll
            for (int mi = 0; mi < 4; mi++) {
                int r0 = wm * 64 + mi * 16 + (lane >> 2);
                af[mi][0] = __float_as_uint(As_[r0 * 36 + k0]);
                af[mi][1] = __float_as_uint(As_[(r0 + 8) * 36 + k0]);
                af[mi][2] = __float_as_uint(As_[r0 * 36 + k0 + 4]);
                af[mi][3] = __float_as_uint(As_[(r0 + 8) * 36 + k0 + 4]);
            }
#pragma unroll
            for (int ni = 0; ni < 4; ni++) {
                int c0 = wn * 32 + ni * 8 + (lane >> 2);
                bf[ni][0] = __float_as_uint(Bs_[c0 * 36 + k0]);
                bf[ni][1] = __float_as_uint(Bs_[c0 * 36 + k0 + 4]);
            }
#pragma unroll
            for (int mi = 0; mi < 4; mi++)
#pragma unroll
                for (int ni = 0; ni < 4; ni++) mma_tf32(acc[mi][ni], af[mi], bf[ni]);
        }
        __syncthreads();
    }
#pragma unroll
    for (int mi = 0; mi < 4; mi++)
#pragma unroll
        for (int ni = 0; ni < 4; ni++)
#pragma unroll
            for (int rr = 0; rr < 2; rr++) {
                int g = by * 128 + wm * 64 + mi * 16 + (lane >> 2) + rr * 8;
                int cb = bx * 128 + wn * 32 + ni * 8 + 2 * (lane & 3);
                int t = cb >> 5, b = cb & 31;
                float bias = bih[g];
                size_t off = ((size_t)dir * TT + t) * (size_t)(G3 * BATCH) + (size_t)g * BATCH + b;
                float2 v;
                v.x = acc[mi][ni][rr * 2 + 0] + bias;
                v.y = acc[mi][ni][rr * 2 + 1] + bias;
                *reinterpret_cast<float2*>(d_xp + off) = v;
            }
}

// ---------------- kernel 3: persistent recurrence, pipelined dataflow sync ----------------
#define REC_SMEM_FLOATS (12288 + 16384 + 3072 + 48)
#define REC_SMEM_BYTES  (REC_SMEM_FLOATS * 4)

__global__ void __launch_bounds__(256, 1)
rec_kernel(const float* __restrict__ bhhf, const float* __restrict__ bhhb,
           float* __restrict__ out) {
    extern __shared__ float smf[];
    float2* sRed2 = reinterpret_cast<float2*>(smf);   // [w][mi][ni][rr][lane] float2
    float*  sB    = smf + 12288;                       // h(s) image, fragment order
    float*  sXp   = smf + 12288 + 16384;               // [2][48][32]
    float*  sBias = sXp + 3072;

    const int c = blockIdx.x, dir = blockIdx.y;
    const int tid = threadIdx.x, lane = tid & 31, w = tid >> 5;
    const int c16 = c * 16;

    // register-resident W fragments: warp w owns kk = 8w .. 8w+7
    float4 aw[8][3];
    {
        const float4* wsrc = reinterpret_cast<const float4*>(
            d_whpf + ((size_t)(dir * NCTA_PER_DIR + c)) * 64 * 384);
#pragma unroll
        for (int q = 0; q < 8; q++)
#pragma unroll
            for (int mi = 0; mi < 3; mi++)
                aw[q][mi] = wsrc[((w * 8 + q) * 3 + mi) * 32 + lane];
    }
    if (tid < 48) sBias[tid] = (dir ? bhhb : bhhf)[gate_row(c, tid)];
    __syncthreads();

    float* hbase = d_h + (size_t)dir * 4 * 16384;
    unsigned* f1 = d_f1 + dir * 1024;   // [cta][32-pad]
    unsigned* f2 = d_f2 + dir * 1024;

    // prologue: issue h(0) chunk (slot 0, zeroed) and xp(0)
    {
        const float* src = hbase + w * 2048;   // slot 0
        float* dst = sB + w * 2048;
#pragma unroll
        for (int r = 0; r < 16; r++)
            cp16(dst + (lane + r * 32) * 4, src + (lane + r * 32) * 4);
        cp_commit();
        const int t0 = dir ? (TT - 1) : 0;
        const float* xps = d_xp + ((size_t)dir * TT + t0) * (size_t)(G3 * BATCH);
        for (int o = tid; o < 384; o += 256) {
            int j = o >> 3, seg = o & 7;
            cp16(&sXp[(j * 32 + seg * 4)], xps + (size_t)gate_row(c, j) * BATCH + seg * 4);
        }
        cp_commit();
    }

    const int we_ni = w & 3, we_rr = w >> 2;

    for (int s = 0; s < TT; s++) {
        const int t = dir ? (TT - 1 - s) : s;
        float* hwr = hbase + (size_t)((s + 1) & 3) * 16384;

        // prefetch write-gate flags (checked before h store; usually satisfied)
        unsigned v2 = ldrlx(f2 + lane * 32);

        cp_wait<0>();   // h(s) chunk + xp(s) resident

        float acc[3][4][4];
#pragma unroll
        for (int mi = 0; mi < 3; mi++)
#pragma unroll
            for (int ni = 0; ni < 4; ni++)
#pragma unroll
                for (int k = 0; k < 4; k++) acc[mi][ni][k] = 0.f;

#pragma unroll
        for (int q = 0; q < 8; q++) {
            const int base = (w * 8 + q) * 256 + (lane >> 2) * 8 + (lane & 3) * 2;
            float2 bf[4];
#pragma unroll
            for (int ni = 0; ni < 4; ni++)
                bf[ni] = *reinterpret_cast<const float2*>(&sB[base + ni * 64]);
#pragma unroll
            for (int mi = 0; mi < 3; mi++)
#pragma unroll
                for (int ni = 0; ni < 4; ni++)
                    mma_tf32_f(acc[mi][ni], aw[q][mi], bf[ni]);
        }

        // partials: [w][mi][ni][rr][lane] float2
#pragma unroll
        for (int mi = 0; mi < 3; mi++)
#pragma unroll
            for (int ni = 0; ni < 4; ni++) {
                sRed2[(((w * 3 + mi) * 4 + ni) * 2 + 0) * 32 + lane] =
                    make_float2(acc[mi][ni][0], acc[mi][ni][1]);
                sRed2[(((w * 3 + mi) * 4 + ni) * 2 + 1) * 32 + lane] =
                    make_float2(acc[mi][ni][2], acc[mi][ni][3]);
            }
        __syncthreads();   // sync1: partials visible; all global h(s) reads complete

        if (tid == 0) strlx(f2 + c * 32, (unsigned)(s + 1));   // my reads of h(s) done
        if (s > 2) {
            const unsigned tgt = (unsigned)(s - 2);            // readers of h(s-3) done
            while (__any_sync(0xffffffffu, v2 < tgt))
                v2 = ldrlx(f2 + lane * 32);                    // slack-gated, normally free
        }

        // epilogue, all 8 warps: ni=we_ni, row-half=we_rr -> 2 elements/thread
        float esum[3][2];
#pragma unroll
        for (int mi = 0; mi < 3; mi++) {
            float2 a0 = sRed2[(((0 * 3 + mi) * 4 + we_ni) * 2 + we_rr) * 32 + lane];
#pragma unroll
            for (int ww = 1; ww < 8; ww++) {
                float2 p = sRed2[(((ww * 3 + mi) * 4 + we_ni) * 2 + we_rr) * 32 + lane];
                a0.x += p.x; a0.y += p.y;
            }
            esum[mi][0] = a0.x; esum[mi][1] = a0.y;
        }
        const int row = we_rr * 8 + (lane >> 2);
        const int kg = c16 + row;
        const float* xpb = sXp + (s & 1) * 1536;
        float hnew2[2];
#pragma unroll
        for (int cc = 0; cc < 2; cc++) {
            int b = we_ni * 8 + 2 * (lane & 3) + cc;
            float rpre = esum[0][cc] + sBias[row];
            float zpre = esum[1][cc] + sBias[16 + row];
            float npre = esum[2][cc] + sBias[32 + row];
            float xr  = xpb[row * 32 + b];
            float xz  = xpb[(16 + row) * 32 + b];
            float xnv = xpb[(32 + row) * 32 + b];
            float rg = 1.0f / (1.0f + __expf(-(xr + rpre)));
            float zg = 1.0f / (1.0f + __expf(-(xz + zpre)));
            float narg = xnv + rg * npre;
            float ng = 2.0f / (1.0f + __expf(-2.0f * narg)) - 1.0f;   // tanh
            int hoff = (kg >> 3) * 256 + b * 8 + (kg & 3) * 2 + ((kg >> 2) & 1);
            float hold = sB[hoff];
            float hnew = (1.0f - zg) * ng + zg * hold;
            hwr[hoff] = hnew;
            hnew2[cc] = hnew;
        }
        __syncthreads();   // sync2: all h(s+1) stores issued; all sB reads done
        if (tid == 0) {
            __threadfence();                                    // single-thread release (cumulative)
            strlx(f1 + c * 32, (unsigned)(s + 1));              // publish h(s+1)
        }

        // ---- pipelined: poll f1(s+1) (4 lanes) and issue h(s+1)+xp(s+1) loads ----
        if (s + 1 < TT) {
            const unsigned tgt = (unsigned)(s + 1);
            unsigned v = tgt;
            do {
                if (lane < 4) v = ldacq(f1 + (4 * w + lane) * 32);
            } while (__ballot_sync(0xffffffffu, (lane < 4) && (v < tgt)) != 0);

            const float* src = hbase + (size_t)((s + 1) & 3) * 16384 + w * 2048;
            float* dst = sB + w * 2048;
#pragma unroll
            for (int r = 0; r < 16; r++)
                cp16(dst + (lane + r * 32) * 4, src + (lane + r * 32) * 4);
            cp_commit();

            const int tn = dir ? (TT - 2 - s) : (s + 1);
            const float* xps = d_xp + ((size_t)dir * TT + tn) * (size_t)(G3 * BATCH);
            float* xdst = sXp + ((s + 1) & 1) * 1536;
            for (int o = tid; o < 384; o += 256) {
                int j = o >> 3, seg = o & 7;
                cp16(xdst + j * 32 + seg * 4, xps + (size_t)gate_row(c, j) * BATCH + seg * 4);
            }
            cp_commit();
        }

        // GELU + output stores: overlapped with the in-flight cp.async
#pragma unroll
        for (int cc = 0; cc < 2; cc++) {
            int b = we_ni * 8 + 2 * (lane & 3) + cc;
            float hnew = hnew2[cc];
            float g = 0.5f * hnew * (1.0f + erff(hnew * 0.70710678118f));
            out[((size_t)b * TT + t) * (size_t)(2 * HH) + (size_t)dir * HH + kg] = g;
        }
    }
}

// ---------------- launcher ----------------
extern "C" void kernel_launch(void* const* d_in, const int* in_sizes, int n_in,
                              void* d_out, int out_size) {
    const float* x       = (const float*)d_in[0];
    const float* ln_g    = (const float*)d_in[1];
    const float* ln_b    = (const float*)d_in[2];
    const float* w_ih_f  = (const float*)d_in[3];
    const float* w_hh_f  = (const float*)d_in[4];
    const float* b_ih_f  = (const float*)d_in[5];
    const float* b_hh_f  = (const float*)d_in[6];
    const float* w_ih_b  = (const float*)d_in[7];
    const float* w_hh_b  = (const float*)d_in[8];
    const float* b_ih_b  = (const float*)d_in[9];
    const float* b_hh_b  = (const float*)d_in[10];
    float* out = (float*)d_out;

    static bool attr_done = false;
    if (!attr_done) {
        cudaFuncSetAttribute(gemm_kernel, cudaFuncAttributeMaxDynamicSharedMemorySize,
                             4 * GEMM_BUF_FLOATS * 4);
        cudaFuncSetAttribute(rec_kernel, cudaFuncAttributeMaxDynamicSharedMemorySize,
                             REC_SMEM_BYTES);
        attr_done = true;
    }

    prep_kernel<<<2048, 256>>>(w_ih_f, w_hh_f, w_ih_b, w_hh_b);
    ln_kernel<<<BATCH * TT, 128>>>(x, ln_g, ln_b);
    gemm_kernel<<<dim3(256, 12, 2), 256, 4 * GEMM_BUF_FLOATS * 4>>>(b_ih_f, b_ih_b);
    rec_kernel<<<dim3(NCTA_PER_DIR, 2), 256, REC_SMEM_BYTES>>>(b_hh_f, b_hh_b, out);
}

// round 8
// speedup vs baseline: 1.0321x; 1.0321x over previous
#include <cuda_runtime.h>
#include <cuda_bf16.h>
#include <cstdint>
#include <cstddef>

#define BATCH 32
#define TT    1024
#define II    512
#define HH    512
#define G3    1536
#define NCTA_PER_DIR 32

// ---------------- device scratch ----------------
__device__ float d_xn[(size_t)BATCH * TT * II];
__device__ float d_xp[(size_t)2 * TT * G3 * BATCH];
__device__ float d_wihr[2 * G3 * II];
__device__ float d_whpf[2 * NCTA_PER_DIR * 64 * 384];
__device__ float d_h[2 * 4 * 16384];                    // h 4-deep ring [dir][buf][16384]
__device__ unsigned int d_f1[2 * 32 * 32];              // produce flags, 128B padded
__device__ unsigned int d_f2[2 * 32 * 32];              // consume flags, 128B padded

// ---------------- helpers ----------------
__device__ __forceinline__ float tf32r(float x) {
    uint32_t u; asm("cvt.rna.tf32.f32 %0, %1;" : "=r"(u) : "f"(x));
    return __uint_as_float(u);
}
__device__ __forceinline__ void cp16(void* smem_dst, const void* gmem_src) {
    uint32_t s = (uint32_t)__cvta_generic_to_shared(smem_dst);
    asm volatile("cp.async.cg.shared.global [%0], [%1], 16;" :: "r"(s), "l"(gmem_src));
}
__device__ __forceinline__ void cp_commit() { asm volatile("cp.async.commit_group;"); }
template <int N> __device__ __forceinline__ void cp_wait() {
    asm volatile("cp.async.wait_group %0;" :: "n"(N));
}
__device__ __forceinline__ unsigned ldacq(const unsigned* p) {
    unsigned v; asm volatile("ld.acquire.gpu.global.u32 %0, [%1];" : "=r"(v) : "l"(p)); return v;
}
__device__ __forceinline__ unsigned ldrlx(const unsigned* p) {
    unsigned v; asm volatile("ld.relaxed.gpu.global.u32 %0, [%1];" : "=r"(v) : "l"(p)); return v;
}
__device__ __forceinline__ void strlx(unsigned* p, unsigned v) {
    asm volatile("st.relaxed.gpu.global.u32 [%0], %1;" :: "l"(p), "r"(v));
}
__device__ __forceinline__ void mma_tf32(float* d, const uint32_t* a, const uint32_t* b) {
    asm volatile(
        "mma.sync.aligned.m16n8k8.row.col.f32.tf32.tf32.f32 "
        "{%0,%1,%2,%3},{%4,%5,%6,%7},{%8,%9},{%0,%1,%2,%3};"
        : "+f"(d[0]), "+f"(d[1]), "+f"(d[2]), "+f"(d[3])
        : "r"(a[0]), "r"(a[1]), "r"(a[2]), "r"(a[3]), "r"(b[0]), "r"(b[1]));
}
__device__ __forceinline__ void mma_tf32_f(float* d, const float4& a, const float2& b) {
    asm volatile(
        "mma.sync.aligned.m16n8k8.row.col.f32.tf32.tf32.f32 "
        "{%0,%1,%2,%3},{%4,%5,%6,%7},{%8,%9},{%0,%1,%2,%3};"
        : "+f"(d[0]), "+f"(d[1]), "+f"(d[2]), "+f"(d[3])
        : "r"(__float_as_uint(a.x)), "r"(__float_as_uint(a.y)),
          "r"(__float_as_uint(a.z)), "r"(__float_as_uint(a.w)),
          "r"(__float_as_uint(b.x)), "r"(__float_as_uint(b.y)));
}
__device__ __forceinline__ int gate_row(int c, int j) {
    return (j < 16) ? (c * 16 + j)
         : (j < 32) ? (512 + c * 16 + (j - 16))
                    : (1024 + c * 16 + (j - 32));
}

// ---------------- kernel 0: prep ----------------
__global__ void prep_kernel(const float* __restrict__ wihf, const float* __restrict__ whhf,
                            const float* __restrict__ wihb, const float* __restrict__ whhb) {
    int idx = blockIdx.x * blockDim.x + threadIdx.x;
    int stride = gridDim.x * blockDim.x;
    for (int i = idx; i < 2 * G3 * II; i += stride) {
        int dir = i / (G3 * II);
        int r = i - dir * (G3 * II);
        d_wihr[i] = tf32r((dir ? wihb : wihf)[r]);
    }
    for (int i = idx; i < 2 * NCTA_PER_DIR * 64 * 384; i += stride) {
        int reg  = i & 3;
        int lane = (i >> 2) & 31;
        int mi   = (i % 384) / 128;
        int kk   = (i / 384) & 63;
        int c    = (i / (384 * 64)) % NCTA_PER_DIR;
        int dir  = i / (384 * 64 * NCTA_PER_DIR);
        int j = mi * 16 + (lane >> 2) + 8 * (reg & 1);
        int k = kk * 8 + (lane & 3) + 4 * (reg >> 1);
        const float* w = dir ? whhb : whhf;
        d_whpf[i] = tf32r(w[gate_row(c, j) * II + k]);
    }
    for (int i = idx; i < 2 * 4 * 16384; i += stride) d_h[i] = 0.0f;
    for (int i = idx; i < 2 * 32 * 32; i += stride) { d_f1[i] = 0u; d_f2[i] = 0u; }
}

// ---------------- kernel 1: LayerNorm ----------------
__global__ void ln_kernel(const float* __restrict__ x, const float* __restrict__ gamma,
                          const float* __restrict__ beta) {
    int row = blockIdx.x;
    const float* xr = x + (size_t)row * II;
    int tid = threadIdx.x;
    float v[4]; float s = 0.f, q = 0.f;
#pragma unroll
    for (int k = 0; k < 4; k++) {
        v[k] = xr[tid + 128 * k];
        s += v[k]; q += v[k] * v[k];
    }
#pragma unroll
    for (int o = 16; o > 0; o >>= 1) {
        s += __shfl_xor_sync(0xffffffffu, s, o);
        q += __shfl_xor_sync(0xffffffffu, q, o);
    }
    __shared__ float ws[4], wq[4];
    if ((tid & 31) == 0) { ws[tid >> 5] = s; wq[tid >> 5] = q; }
    __syncthreads();
    s = ws[0] + ws[1] + ws[2] + ws[3];
    q = wq[0] + wq[1] + wq[2] + wq[3];
    float mu = s * (1.0f / 512.0f);
    float var = q * (1.0f / 512.0f) - mu * mu;
    float rstd = rsqrtf(var + 1e-5f);
#pragma unroll
    for (int k = 0; k < 4; k++) {
        int i = tid + 128 * k;
        d_xn[(size_t)row * II + i] = tf32r((v[k] - mu) * rstd * gamma[i] + beta[i]);
    }
}

// ---------------- kernel 2: input-projection GEMM (smem-staged coalesced epilogue) ----------------
#define GEMM_BUF_FLOATS (128 * 36)
__global__ void __launch_bounds__(256)
gemm_kernel(const float* __restrict__ bihf, const float* __restrict__ bihb) {
    extern __shared__ float smem[];
    float* As = smem;
    float* Bs = smem + 2 * GEMM_BUF_FLOATS;
    int bx = blockIdx.x, by = blockIdx.y, dir = blockIdx.z;
    int tid = threadIdx.x, lane = tid & 31, wid = tid >> 5;
    int wm = wid & 1, wn = wid >> 1;
    const float* bih = dir ? bihb : bihf;
    const float* Abase = d_wihr + (size_t)dir * G3 * II + (size_t)(by * 128) * II;

    auto load_tiles = [&](int kb, int buf) {
        float* As_ = As + buf * GEMM_BUF_FLOATS;
        float* Bs_ = Bs + buf * GEMM_BUF_FLOATS;
#pragma unroll
        for (int u = 0; u < 4; u++) {
            int o = tid + 256 * u;
            int row = o >> 3, seg = o & 7;
            cp16(&As_[row * 36 + seg * 4], Abase + (size_t)row * II + kb * 32 + seg * 4);
        }
#pragma unroll
        for (int u = 0; u < 4; u++) {
            int o = tid + 256 * u;
            int col = o >> 3, seg = o & 7;
            int n = bx * 128 + col;
            int t = n >> 5, b = n & 31;
            cp16(&Bs_[col * 36 + seg * 4], d_xn + ((size_t)b * TT + t) * II + kb * 32 + seg * 4);
        }
    };

    float acc[4][4][4];
#pragma unroll
    for (int i = 0; i < 4; i++)
#pragma unroll
        for (int j = 0; j < 4; j++)
#pragma unroll
            for (int k = 0; k < 4; k++) acc[i][j][k] = 0.f;

    load_tiles(0, 0); cp_commit();
    for (int kb = 0; kb < 16; kb++) {
        if (kb + 1 < 16) { load_tiles(kb + 1, (kb + 1) & 1); cp_commit(); cp_wait<1>(); }
        else cp_wait<0>();
        __syncthreads();
        float* As_ = As + (kb & 1) * GEMM_BUF_FLOATS;
        float* Bs_ = Bs + (kb & 1) * GEMM_BUF_FLOATS;
#pragma unroll
        for (int ks = 0; ks < 4; ks++) {
            int k0 = ks * 8 + (lane & 3);
            uint32_t af[4][4], bf[4][2];
#pragma unroll
            for (int mi = 0; mi < 4; mi++) {
                int r0 = wm * 64 + mi * 16 + (lane >> 2);
                af[mi][0] = __float_as_uint(As_[r0 * 36 + k0]);
                af[mi][1] = __float_as_uint(As_[(r0 + 8) * 36 + k0]);
                af[mi][2] = __float_as_uint(As_[r0 * 36 + k0 + 4]);
                af[mi][3] = __float_as_uint(As_[(r0 + 8) * 36 + k0 + 4]);
            }
#pragma unroll
            for (int ni = 0; ni < 4; ni++) {
                int c0 = wn * 32 + ni * 8 + (lane >> 2);
                bf[ni][0] = __float_as_uint(Bs_[c0 * 36 + k0]);
                bf[ni][1] = __float_as_uint(Bs_[c0 * 36 + k0 + 4]);
            }
#pragma unroll
            for (int mi = 0; mi < 4; mi++)
#pragma unroll
                for (int ni = 0; ni < 4; ni++) mma_tf32(acc[mi][ni], af[mi], bf[ni]);
        }
        __syncthreads();
    }

    // ---- epilogue: stage C tile (128g x 128n, pad 132) in smem, then coalesced float4 sweep ----
    float* sC = smem;   // 128*132 floats = 67584 B <= 73728 B allocated
#pragma unroll
    for (int mi = 0; mi < 4; mi++)
#pragma unroll
        for (int ni = 0; ni < 4; ni++)
#pragma unroll
            for (int rr = 0; rr < 2; rr++) {
                int gl = wm * 64 + mi * 16 + (lane >> 2) + rr * 8;
                int nl = wn * 32 + ni * 8 + 2 * (lane & 3);
                *reinterpret_cast<float2*>(&sC[gl * 132 + nl]) =
                    make_float2(acc[mi][ni][rr * 2 + 0], acc[mi][ni][rr * 2 + 1]);
            }
    __syncthreads();

    const int t0 = bx * 4;
    const size_t dbase = (size_t)dir * TT * (size_t)(G3 * BATCH);
#pragma unroll
    for (int k2 = 0; k2 < 16; k2++) {
        int idx = tid + 256 * k2;
        int g  = idx >> 5;          // 0..127
        int n4 = idx & 31;          // float4 index within 128 n-cols
        int tl = n4 >> 3;           // 0..3  (t within tile)
        int b  = (n4 & 7) * 4;      // 0..28
        float4 v = *reinterpret_cast<const float4*>(&sC[g * 132 + n4 * 4]);
        float bias = bih[by * 128 + g];
        v.x += bias; v.y += bias; v.z += bias; v.w += bias;
        size_t off = dbase + (size_t)(t0 + tl) * (G3 * BATCH) + (size_t)(by * 128 + g) * BATCH + b;
        *reinterpret_cast<float4*>(d_xp + off) = v;
    }
}

// ---------------- kernel 3: persistent recurrence, dataflow-synced, 4-deep h ring ----------------
#define REC_SMEM_FLOATS (12288 + 16384 + 3072 + 48)
#define REC_SMEM_BYTES  (REC_SMEM_FLOATS * 4)

__global__ void __launch_bounds__(256, 1)
rec_kernel(const float* __restrict__ bhhf, const float* __restrict__ bhhb,
           float* __restrict__ out) {
    extern __shared__ float smf[];
    float2* sRed2 = reinterpret_cast<float2*>(smf);   // [w][mi][ni][rr][lane] float2
    float*  sB    = smf + 12288;                       // h(s) image, fragment order
    float*  sXp   = smf + 12288 + 16384;               // [2][48][32]
    float*  sBias = sXp + 3072;

    const int c = blockIdx.x, dir = blockIdx.y;
    const int tid = threadIdx.x, lane = tid & 31, w = tid >> 5;
    const int c16 = c * 16;

    // register-resident W fragments: warp w owns kk = 8w .. 8w+7
    float4 aw[8][3];
    {
        const float4* wsrc = reinterpret_cast<const float4*>(
            d_whpf + ((size_t)(dir * NCTA_PER_DIR + c)) * 64 * 384);
#pragma unroll
        for (int q = 0; q < 8; q++)
#pragma unroll
            for (int mi = 0; mi < 3; mi++)
                aw[q][mi] = wsrc[((w * 8 + q) * 3 + mi) * 32 + lane];
    }
    if (tid < 48) sBias[tid] = (dir ? bhhb : bhhf)[gate_row(c, tid)];
    __syncthreads();

    float* hbase = d_h + (size_t)dir * 4 * 16384;
    unsigned* f1 = d_f1 + dir * 1024;   // [cta][32-pad]
    unsigned* f2 = d_f2 + dir * 1024;

    // prologue: prefetch xp(0) into buf 0
    {
        const int t0 = dir ? (TT - 1) : 0;
        const float* xps = d_xp + ((size_t)dir * TT + t0) * (size_t)(G3 * BATCH);
        for (int o = tid; o < 384; o += 256) {
            int j = o >> 3, seg = o & 7;
            cp16(&sXp[(j * 32 + seg * 4)], xps + (size_t)gate_row(c, j) * BATCH + seg * 4);
        }
        cp_commit();
    }

    const int we_ni = w & 3, we_rr = w >> 2;

    for (int s = 0; s < TT; s++) {
        const int t = dir ? (TT - 1 - s) : s;
        const float* hrd = hbase + (size_t)(s & 3) * 16384;
        float* hwr = hbase + (size_t)((s + 1) & 3) * 16384;

        // per-warp: wait for my 4 source CTAs to publish h(s)
        if (s > 0) {
            const unsigned* fp = f1 + (4 * w + (lane & 3)) * 32;
            unsigned v;
            do { v = ldacq(fp); } while (__any_sync(0xffffffffu, v < (unsigned)s));
        }
        // my 8KB h chunk
        {
            const float* src = hrd + w * 2048;
            float* dst = sB + w * 2048;
#pragma unroll
            for (int r = 0; r < 16; r++)
                cp16(dst + (lane + r * 32) * 4, src + (lane + r * 32) * 4);
            cp_commit();
        }
        // prefetch write-gate flags (verified later; 4-deep ring -> target s-2)
        unsigned v2 = ldrlx(f2 + lane * 32);
        // prefetch xp(s+1)
        {
            int tn = dir ? (TT - 2 - s) : (s + 1);
            if (tn < 0) tn = 0; if (tn >= TT) tn = TT - 1;
            const float* xps = d_xp + ((size_t)dir * TT + tn) * (size_t)(G3 * BATCH);
            float* dst = sXp + ((s + 1) & 1) * 1536;
            for (int o = tid; o < 384; o += 256) {
                int j = o >> 3, seg = o & 7;
                cp16(dst + j * 32 + seg * 4, xps + (size_t)gate_row(c, j) * BATCH + seg * 4);
            }
            cp_commit();
        }

        float acc[3][4][4];
#pragma unroll
        for (int mi = 0; mi < 3; mi++)
#pragma unroll
            for (int ni = 0; ni < 4; ni++)
#pragma unroll
                for (int k = 0; k < 4; k++) acc[mi][ni][k] = 0.f;

        cp_wait<1>();   // h(s) + xp(s) done; xp(s+1) in flight

#pragma unroll
        for (int q = 0; q < 8; q++) {
            const int base = (w * 8 + q) * 256 + (lane >> 2) * 8 + (lane & 3) * 2;
            float2 bf[4];
#pragma unroll
            for (int ni = 0; ni < 4; ni++)
                bf[ni] = *reinterpret_cast<const float2*>(&sB[base + ni * 64]);
#pragma unroll
            for (int mi = 0; mi < 3; mi++)
#pragma unroll
                for (int ni = 0; ni < 4; ni++)
                    mma_tf32_f(acc[mi][ni], aw[q][mi], bf[ni]);
        }

        // partials: [w][mi][ni][rr][lane] float2
#pragma unroll
        for (int mi = 0; mi < 3; mi++)
#pragma unroll
            for (int ni = 0; ni < 4; ni++) {
                sRed2[(((w * 3 + mi) * 4 + ni) * 2 + 0) * 32 + lane] =
                    make_float2(acc[mi][ni][0], acc[mi][ni][1]);
                sRed2[(((w * 3 + mi) * 4 + ni) * 2 + 1) * 32 + lane] =
                    make_float2(acc[mi][ni][2], acc[mi][ni][3]);
            }
        __syncthreads();   // sync1: partials visible; all global h(s) reads complete

        if (tid == 0) strlx(f2 + c * 32, (unsigned)(s + 1));   // my reads of h(s) done
        if (s > 2) {
            const unsigned tgt = (unsigned)(s - 2);            // readers of h(s-3) done
            while (__any_sync(0xffffffffu, v2 < tgt))
                v2 = ldrlx(f2 + lane * 32);                    // slack-gated, normally free
        }

        // epilogue, all 8 warps: ni=we_ni, row-half=we_rr -> 2 elements/thread
        float esum[3][2];
#pragma unroll
        for (int mi = 0; mi < 3; mi++) {
            float2 a0 = sRed2[(((0 * 3 + mi) * 4 + we_ni) * 2 + we_rr) * 32 + lane];
#pragma unroll
            for (int ww = 1; ww < 8; ww++) {
                float2 p = sRed2[(((ww * 3 + mi) * 4 + we_ni) * 2 + we_rr) * 32 + lane];
                a0.x += p.x; a0.y += p.y;
            }
            esum[mi][0] = a0.x; esum[mi][1] = a0.y;
        }
        const int row = we_rr * 8 + (lane >> 2);
        const int kg = c16 + row;
        const float* xpb = sXp + (s & 1) * 1536;
        float hnew2[2];
#pragma unroll
        for (int cc = 0; cc < 2; cc++) {
            int b = we_ni * 8 + 2 * (lane & 3) + cc;
            float rpre = esum[0][cc] + sBias[row];
            float zpre = esum[1][cc] + sBias[16 + row];
            float npre = esum[2][cc] + sBias[32 + row];
            float xr  = xpb[row * 32 + b];
            float xz  = xpb[(16 + row) * 32 + b];
            float xnv = xpb[(32 + row) * 32 + b];
            float rg = 1.0f / (1.0f + __expf(-(xr + rpre)));
            float zg = 1.0f / (1.0f + __expf(-(xz + zpre)));
            float narg = xnv + rg * npre;
            float ng = 2.0f / (1.0f + __expf(-2.0f * narg)) - 1.0f;   // tanh
            int hoff = (kg >> 3) * 256 + b * 8 + (kg & 3) * 2 + ((kg >> 2) & 1);
            float hold = sB[hoff];
            float hnew = (1.0f - zg) * ng + zg * hold;
            hwr[hoff] = hnew;
            hnew2[cc] = hnew;
        }
        __syncthreads();   // sync2: all h(s+1) stores issued (CTA-visible)
        if (tid == 0) {
            __threadfence();                                    // single-thread release (cumulative)
            strlx(f1 + c * 32, (unsigned)(s + 1));              // publish h(s+1)
        }

        // GELU + output (off the critical path)
#pragma unroll
        for (int cc = 0; cc < 2; cc++) {
            int b = we_ni * 8 + 2 * (lane & 3) + cc;
            float hnew = hnew2[cc];
            float g = 0.5f * hnew * (1.0f + erff(hnew * 0.70710678118f));
            out[((size_t)b * TT + t) * (size_t)(2 * HH) + (size_t)dir * HH + kg] = g;
        }
    }
}

// ---------------- launcher ----------------
extern "C" void kernel_launch(void* const* d_in, const int* in_sizes, int n_in,
                              void* d_out, int out_size) {
    const float* x       = (const float*)d_in[0];
    const float* ln_g    = (const float*)d_in[1];
    const float* ln_b    = (const float*)d_in[2];
    const float* w_ih_f  = (const float*)d_in[3];
    const float* w_hh_f  = (const float*)d_in[4];
    const float* b_ih_f  = (const float*)d_in[5];
    const float* b_hh_f  = (const float*)d_in[6];
    const float* w_ih_b  = (const float*)d_in[7];
    const float* w_hh_b  = (const float*)d_in[8];
    const float* b_ih_b  = (const float*)d_in[9];
    const float* b_hh_b  = (const float*)d_in[10];
    float* out = (float*)d_out;

    static bool attr_done = false;
    if (!attr_done) {
        cudaFuncSetAttribute(gemm_kernel, cudaFuncAttributeMaxDynamicSharedMemorySize,
                             4 * GEMM_BUF_FLOATS * 4);
        cudaFuncSetAttribute(rec_kernel, cudaFuncAttributeMaxDynamicSharedMemorySize,
                             REC_SMEM_BYTES);
        attr_done = true;
    }

    prep_kernel<<<2048, 256>>>(w_ih_f, w_hh_f, w_ih_b, w_hh_b);
    ln_kernel<<<BATCH * TT, 128>>>(x, ln_g, ln_b);
    gemm_kernel<<<dim3(256, 12, 2), 256, 4 * GEMM_BUF_FLOATS * 4>>>(b_ih_f, b_ih_b);
    rec_kernel<<<dim3(NCTA_PER_DIR, 2), 256, REC_SMEM_BYTES>>>(b_hh_f, b_hh_b, out);
}

// round 9
// speedup vs baseline: 1.1143x; 1.0797x over previous
#include <cuda_runtime.h>
#include <cuda_bf16.h>
#include <cstdint>
#include <cstddef>

#define BATCH 32
#define TT    1024
#define II    512
#define HH    512
#define G3    1536
#define NCTA_PER_DIR 32

// ---------------- device scratch ----------------
__device__ float d_xn[(size_t)BATCH * TT * II];
__device__ float d_xp[(size_t)2 * TT * G3 * BATCH];
__device__ float d_wihr[2 * G3 * II];
__device__ float d_whpf[2 * NCTA_PER_DIR * 64 * 384];
__device__ float d_h[2 * 4 * 16384];                    // h 4-deep ring [dir][buf][16384]
__device__ unsigned int d_f1[2 * 32 * 32];              // produce flags, 128B padded

// ---------------- helpers ----------------
__device__ __forceinline__ float tf32r(float x) {
    uint32_t u; asm("cvt.rna.tf32.f32 %0, %1;" : "=r"(u) : "f"(x));
    return __uint_as_float(u);
}
__device__ __forceinline__ void cp16(void* smem_dst, const void* gmem_src) {
    uint32_t s = (uint32_t)__cvta_generic_to_shared(smem_dst);
    asm volatile("cp.async.cg.shared.global [%0], [%1], 16;" :: "r"(s), "l"(gmem_src));
}
__device__ __forceinline__ void cp_commit() { asm volatile("cp.async.commit_group;"); }
template <int N> __device__ __forceinline__ void cp_wait() {
    asm volatile("cp.async.wait_group %0;" :: "n"(N));
}
__device__ __forceinline__ unsigned ldacq(const unsigned* p) {
    unsigned v; asm volatile("ld.acquire.gpu.global.u32 %0, [%1];" : "=r"(v) : "l"(p)); return v;
}
__device__ __forceinline__ void strlx(unsigned* p, unsigned v) {
    asm volatile("st.relaxed.gpu.global.u32 [%0], %1;" :: "l"(p), "r"(v));
}
__device__ __forceinline__ void mma_tf32(float* d, const uint32_t* a, const uint32_t* b) {
    asm volatile(
        "mma.sync.aligned.m16n8k8.row.col.f32.tf32.tf32.f32 "
        "{%0,%1,%2,%3},{%4,%5,%6,%7},{%8,%9},{%0,%1,%2,%3};"
        : "+f"(d[0]), "+f"(d[1]), "+f"(d[2]), "+f"(d[3])
        : "r"(a[0]), "r"(a[1]), "r"(a[2]), "r"(a[3]), "r"(b[0]), "r"(b[1]));
}
__device__ __forceinline__ void mma_tf32_f(float* d, const float4& a, const float2& b) {
    asm volatile(
        "mma.sync.aligned.m16n8k8.row.col.f32.tf32.tf32.f32 "
        "{%0,%1,%2,%3},{%4,%5,%6,%7},{%8,%9},{%0,%1,%2,%3};"
        : "+f"(d[0]), "+f"(d[1]), "+f"(d[2]), "+f"(d[3])
        : "r"(__float_as_uint(a.x)), "r"(__float_as_uint(a.y)),
          "r"(__float_as_uint(a.z)), "r"(__float_as_uint(a.w)),
          "r"(__float_as_uint(b.x)), "r"(__float_as_uint(b.y)));
}
__device__ __forceinline__ int gate_row(int c, int j) {
    return (j < 16) ? (c * 16 + j)
         : (j < 32) ? (512 + c * 16 + (j - 16))
                    : (1024 + c * 16 + (j - 32));
}

// ---------------- kernel 0: prep ----------------
__global__ void prep_kernel(const float* __restrict__ wihf, const float* __restrict__ whhf,
                            const float* __restrict__ wihb, const float* __restrict__ whhb) {
    int idx = blockIdx.x * blockDim.x + threadIdx.x;
    int stride = gridDim.x * blockDim.x;
    for (int i = idx; i < 2 * G3 * II; i += stride) {
        int dir = i / (G3 * II);
        int r = i - dir * (G3 * II);
        d_wihr[i] = tf32r((dir ? wihb : wihf)[r]);
    }
    for (int i = idx; i < 2 * NCTA_PER_DIR * 64 * 384; i += stride) {
        int reg  = i & 3;
        int lane = (i >> 2) & 31;
        int mi   = (i % 384) / 128;
        int kk   = (i / 384) & 63;
        int c    = (i / (384 * 64)) % NCTA_PER_DIR;
        int dir  = i / (384 * 64 * NCTA_PER_DIR);
        int j = mi * 16 + (lane >> 2) + 8 * (reg & 1);
        int k = kk * 8 + (lane & 3) + 4 * (reg >> 1);
        const float* w = dir ? whhb : whhf;
        d_whpf[i] = tf32r(w[gate_row(c, j) * II + k]);
    }
    for (int i = idx; i < 2 * 4 * 16384; i += stride) d_h[i] = 0.0f;
    for (int i = idx; i < 2 * 32 * 32; i += stride) d_f1[i] = 0u;
}

// ---------------- kernel 1: LayerNorm ----------------
__global__ void ln_kernel(const float* __restrict__ x, const float* __restrict__ gamma,
                          const float* __restrict__ beta) {
    int row = blockIdx.x;
    const float* xr = x + (size_t)row * II;
    int tid = threadIdx.x;
    float v[4]; float s = 0.f, q = 0.f;
#pragma unroll
    for (int k = 0; k < 4; k++) {
        v[k] = xr[tid + 128 * k];
        s += v[k]; q += v[k] * v[k];
    }
#pragma unroll
    for (int o = 16; o > 0; o >>= 1) {
        s += __shfl_xor_sync(0xffffffffu, s, o);
        q += __shfl_xor_sync(0xffffffffu, q, o);
    }
    __shared__ float ws[4], wq[4];
    if ((tid & 31) == 0) { ws[tid >> 5] = s; wq[tid >> 5] = q; }
    __syncthreads();
    s = ws[0] + ws[1] + ws[2] + ws[3];
    q = wq[0] + wq[1] + wq[2] + wq[3];
    float mu = s * (1.0f / 512.0f);
    float var = q * (1.0f / 512.0f) - mu * mu;
    float rstd = rsqrtf(var + 1e-5f);
#pragma unroll
    for (int k = 0; k < 4; k++) {
        int i = tid + 128 * k;
        d_xn[(size_t)row * II + i] = tf32r((v[k] - mu) * rstd * gamma[i] + beta[i]);
    }
}

// ---------------- kernel 2: input-projection GEMM (smem-staged coalesced epilogue) ----------------
#define GEMM_BUF_FLOATS (128 * 36)
__global__ void __launch_bounds__(256)
gemm_kernel(const float* __restrict__ bihf, const float* __restrict__ bihb) {
    extern __shared__ float smem[];
    float* As = smem;
    float* Bs = smem + 2 * GEMM_BUF_FLOATS;
    int bx = blockIdx.x, by = blockIdx.y, dir = blockIdx.z;
    int tid = threadIdx.x, lane = tid & 31, wid = tid >> 5;
    int wm = wid & 1, wn = wid >> 1;
    const float* bih = dir ? bihb : bihf;
    const float* Abase = d_wihr + (size_t)dir * G3 * II + (size_t)(by * 128) * II;

    auto load_tiles = [&](int kb, int buf) {
        float* As_ = As + buf * GEMM_BUF_FLOATS;
        float* Bs_ = Bs + buf * GEMM_BUF_FLOATS;
#pragma unroll
        for (int u = 0; u < 4; u++) {
            int o = tid + 256 * u;
            int row = o >> 3, seg = o & 7;
            cp16(&As_[row * 36 + seg * 4], Abase + (size_t)row * II + kb * 32 + seg * 4);
        }
#pragma unroll
        for (int u = 0; u < 4; u++) {
            int o = tid + 256 * u;
            int col = o >> 3, seg = o & 7;
            int n = bx * 128 + col;
            int t = n >> 5, b = n & 31;
            cp16(&Bs_[col * 36 + seg * 4], d_xn + ((size_t)b * TT + t) * II + kb * 32 + seg * 4);
        }
    };

    float acc[4][4][4];
#pragma unroll
    for (int i = 0; i < 4; i++)
#pragma unroll
        for (int j = 0; j < 4; j++)
#pragma unroll
            for (int k = 0; k < 4; k++) acc[i][j][k] = 0.f;

    load_tiles(0, 0); cp_commit();
    for (int kb = 0; kb < 16; kb++) {
        if (kb + 1 < 16) { load_tiles(kb + 1, (kb + 1) & 1); cp_commit(); cp_wait<1>(); }
        else cp_wait<0>();
        __syncthreads();
        float* As_ = As + (kb & 1) * GEMM_BUF_FLOATS;
        float* Bs_ = Bs + (kb & 1) * GEMM_BUF_FLOATS;
#pragma unroll
        for (int ks = 0; ks < 4; ks++) {
            int k0 = ks * 8 + (lane & 3);
            uint32_t af[4][4], bf[4][2];
#pragma unroll
            for (int mi = 0; mi < 4; mi++) {
                int r0 = wm * 64 + mi * 16 + (lane >> 2);
                af[mi][0] = __float_as_uint(As_[r0 * 36 + k0]);
                af[mi][1] = __float_as_uint(As_[(r0 + 8) * 36 + k0]);
                af[mi][2] = __float_as_uint(As_[r0 * 36 + k0 + 4]);
                af[mi][3] = __float_as_uint(As_[(r0 + 8) * 36 + k0 + 4]);
            }
#pragma unroll
            for (int ni = 0; ni < 4; ni++) {
                int c0 = wn * 32 + ni * 8 + (lane >> 2);
                bf[ni][0] = __float_as_uint(Bs_[c0 * 36 + k0]);
                bf[ni][1] = __float_as_uint(Bs_[c0 * 36 + k0 + 4]);
            }
#pragma unroll
            for (int mi = 0; mi < 4; mi++)
#pragma unroll
                for (int ni = 0; ni < 4; ni++) mma_tf32(acc[mi][ni], af[mi], bf[ni]);
        }
        __syncthreads();
    }

    // ---- epilogue: stage C tile (128g x 128n, pad 132) in smem, then coalesced float4 sweep ----
    float* sC = smem;   // 128*132 floats = 67584 B <= 73728 B allocated
#pragma unroll
    for (int mi = 0; mi < 4; mi++)
#pragma unroll
        for (int ni = 0; ni < 4; ni++)
#pragma unroll
            for (int rr = 0; rr < 2; rr++) {
                int gl = wm * 64 + mi * 16 + (lane >> 2) + rr * 8;
                int nl = wn * 32 + ni * 8 + 2 * (lane & 3);
                *reinterpret_cast<float2*>(&sC[gl * 132 + nl]) =
                    make_float2(acc[mi][ni][rr * 2 + 0], acc[mi][ni][rr * 2 + 1]);
            }
    __syncthreads();

    const int t0 = bx * 4;
    const size_t dbase = (size_t)dir * TT * (size_t)(G3 * BATCH);
#pragma unroll
    for (int k2 = 0; k2 < 16; k2++) {
        int idx = tid + 256 * k2;
        int g  = idx >> 5;          // 0..127
        int n4 = idx & 31;          // float4 index within 128 n-cols
        int tl = n4 >> 3;           // 0..3  (t within tile)
        int b  = (n4 & 7) * 4;      // 0..28
        float4 v = *reinterpret_cast<const float4*>(&sC[g * 132 + n4 * 4]);
        float bias = bih[by * 128 + g];
        v.x += bias; v.y += bias; v.z += bias; v.w += bias;
        size_t off = dbase + (size_t)(t0 + tl) * (G3 * BATCH) + (size_t)(by * 128 + g) * BATCH + b;
        *reinterpret_cast<float4*>(d_xp + off) = v;
    }
}

// ---------------- kernel 3: persistent recurrence, dataflow-synced, staged loads ----------------
#define REC_SMEM_FLOATS (12288 + 16384 + 3072 + 48)
#define REC_SMEM_BYTES  (REC_SMEM_FLOATS * 4)

__global__ void __launch_bounds__(256, 1)
rec_kernel(const float* __restrict__ bhhf, const float* __restrict__ bhhb,
           float* __restrict__ out) {
    extern __shared__ float smf[];
    float2* sRed2 = reinterpret_cast<float2*>(smf);   // [w][mi][ni][rr][lane] float2
    float*  sB    = smf + 12288;                       // h(s) image, fragment order
    float*  sXp   = smf + 12288 + 16384;               // [2][48][32]
    float*  sBias = sXp + 3072;

    const int c = blockIdx.x, dir = blockIdx.y;
    const int tid = threadIdx.x, lane = tid & 31, w = tid >> 5;
    const int c16 = c * 16;

    // register-resident W fragments: warp w owns kk = 8w .. 8w+7
    float4 aw[8][3];
    {
        const float4* wsrc = reinterpret_cast<const float4*>(
            d_whpf + ((size_t)(dir * NCTA_PER_DIR + c)) * 64 * 384);
#pragma unroll
        for (int q = 0; q < 8; q++)
#pragma unroll
            for (int mi = 0; mi < 3; mi++)
                aw[q][mi] = wsrc[((w * 8 + q) * 3 + mi) * 32 + lane];
    }
    if (tid < 48) sBias[tid] = (dir ? bhhb : bhhf)[gate_row(c, tid)];
    __syncthreads();

    float* hbase = d_h + (size_t)dir * 4 * 16384;
    unsigned* f1 = d_f1 + dir * 1024;   // [cta][32-pad]

    // prologue: prefetch xp(0) into buf 0 (one group; matches steady-state accounting)
    {
        const int t0 = dir ? (TT - 1) : 0;
        const float* xps = d_xp + ((size_t)dir * TT + t0) * (size_t)(G3 * BATCH);
        for (int o = tid; o < 384; o += 256) {
            int j = o >> 3, seg = o & 7;
            cp16(&sXp[(j * 32 + seg * 4)], xps + (size_t)gate_row(c, j) * BATCH + seg * 4);
        }
        cp_commit();
    }

    const int we_ni = w & 3, we_rr = w >> 2;

    for (int s = 0; s < TT; s++) {
        const int t = dir ? (TT - 1 - s) : s;
        const float* hrd = hbase + (size_t)(s & 3) * 16384;
        float* hwr = hbase + (size_t)((s + 1) & 3) * 16384;

        // per-warp: wait for my 4 source CTAs to publish h(s)
        if (s > 0) {
            const unsigned* fp = f1 + (4 * w + (lane & 3)) * 32;
            unsigned v;
            do { v = ldacq(fp); } while (__any_sync(0xffffffffu, v < (unsigned)s));
        }
        // my 8KB h chunk as TWO 4KB groups (A: r0-7, B: r8-15)
        {
            const float* src = hrd + w * 2048;
            float* dst = sB + w * 2048;
#pragma unroll
            for (int r = 0; r < 8; r++)
                cp16(dst + (lane + r * 32) * 4, src + (lane + r * 32) * 4);
            cp_commit();
#pragma unroll
            for (int r = 8; r < 16; r++)
                cp16(dst + (lane + r * 32) * 4, src + (lane + r * 32) * 4);
            cp_commit();
        }
        // prefetch xp(s+1)
        {
            int tn = dir ? (TT - 2 - s) : (s + 1);
            if (tn < 0) tn = 0; if (tn >= TT) tn = TT - 1;
            const float* xps = d_xp + ((size_t)dir * TT + tn) * (size_t)(G3 * BATCH);
            float* dst = sXp + ((s + 1) & 1) * 1536;
            for (int o = tid; o < 384; o += 256) {
                int j = o >> 3, seg = o & 7;
                cp16(dst + j * 32 + seg * 4, xps + (size_t)gate_row(c, j) * BATCH + seg * 4);
            }
            cp_commit();
        }
        // pending now: xp(s), A(s), B(s), xp(s+1)

        float acc[3][4][4];
#pragma unroll
        for (int mi = 0; mi < 3; mi++)
#pragma unroll
            for (int ni = 0; ni < 4; ni++)
#pragma unroll
                for (int k = 0; k < 4; k++) acc[mi][ni][k] = 0.f;

        cp_wait<2>();   // xp(s) + A done; B + xp(s+1) in flight
        __syncwarp();
#pragma unroll
        for (int q = 0; q < 4; q++) {
            const int base = (w * 8 + q) * 256 + (lane >> 2) * 8 + (lane & 3) * 2;
            float2 bf[4];
#pragma unroll
            for (int ni = 0; ni < 4; ni++)
                bf[ni] = *reinterpret_cast<const float2*>(&sB[base + ni * 64]);
#pragma unroll
            for (int mi = 0; mi < 3; mi++)
#pragma unroll
                for (int ni = 0; ni < 4; ni++)
                    mma_tf32_f(acc[mi][ni], aw[q][mi], bf[ni]);
        }
        cp_wait<1>();   // B done; xp(s+1) in flight
        __syncwarp();
#pragma unroll
        for (int q = 4; q < 8; q++) {
            const int base = (w * 8 + q) * 256 + (lane >> 2) * 8 + (lane & 3) * 2;
            float2 bf[4];
#pragma unroll
            for (int ni = 0; ni < 4; ni++)
                bf[ni] = *reinterpret_cast<const float2*>(&sB[base + ni * 64]);
#pragma unroll
            for (int mi = 0; mi < 3; mi++)
#pragma unroll
                for (int ni = 0; ni < 4; ni++)
                    mma_tf32_f(acc[mi][ni], aw[q][mi], bf[ni]);
        }

        // partials: [w][mi][ni][rr][lane] float2
#pragma unroll
        for (int mi = 0; mi < 3; mi++)
#pragma unroll
            for (int ni = 0; ni < 4; ni++) {
                sRed2[(((w * 3 + mi) * 4 + ni) * 2 + 0) * 32 + lane] =
                    make_float2(acc[mi][ni][0], acc[mi][ni][1]);
                sRed2[(((w * 3 + mi) * 4 + ni) * 2 + 1) * 32 + lane] =
                    make_float2(acc[mi][ni][2], acc[mi][ni][3]);
            }
        __syncthreads();   // sync1: partials visible; all global h(s) reads complete

        // NOTE: write-gate (old f2) is provably redundant with the 4-deep ring:
        // passing the f1>=s wait in all warps + sync1 implies every CTA finished
        // step s-1, hence all reads of h(s-3) (the slot h(s+1) overwrites) are done.

        // epilogue, all 8 warps: ni=we_ni, row-half=we_rr -> 2 elements/thread
        float esum[3][2];
#pragma unroll
        for (int mi = 0; mi < 3; mi++) {
            float2 a0 = sRed2[(((0 * 3 + mi) * 4 + we_ni) * 2 + we_rr) * 32 + lane];
#pragma unroll
            for (int ww = 1; ww < 8; ww++) {
                float2 p = sRed2[(((ww * 3 + mi) * 4 + we_ni) * 2 + we_rr) * 32 + lane];
                a0.x += p.x; a0.y += p.y;
            }
            esum[mi][0] = a0.x; esum[mi][1] = a0.y;
        }
        const int row = we_rr * 8 + (lane >> 2);
        const int kg = c16 + row;
        const float* xpb = sXp + (s & 1) * 1536;
        float hnew2[2];
#pragma unroll
        for (int cc = 0; cc < 2; cc++) {
            int b = we_ni * 8 + 2 * (lane & 3) + cc;
            float rpre = esum[0][cc] + sBias[row];
            float zpre = esum[1][cc] + sBias[16 + row];
            float npre = esum[2][cc] + sBias[32 + row];
            float xr  = xpb[row * 32 + b];
            float xz  = xpb[(16 + row) * 32 + b];
            float xnv = xpb[(32 + row) * 32 + b];
            float rg = 1.0f / (1.0f + __expf(-(xr + rpre)));
            float zg = 1.0f / (1.0f + __expf(-(xz + zpre)));
            float narg = xnv + rg * npre;
            float ng = 2.0f / (1.0f + __expf(-2.0f * narg)) - 1.0f;   // tanh
            int hoff = (kg >> 3) * 256 + b * 8 + (kg & 3) * 2 + ((kg >> 2) & 1);
            float hold = sB[hoff];
            float hnew = (1.0f - zg) * ng + zg * hold;
            hwr[hoff] = hnew;
            hnew2[cc] = hnew;
        }
        __syncthreads();   // sync2: all h(s+1) stores issued (CTA-visible)
        if (tid == 0) {
            __threadfence();                                    // single-thread release (cumulative)
            strlx(f1 + c * 32, (unsigned)(s + 1));              // publish h(s+1)
        }

        // GELU + output (off the critical path)
#pragma unroll
        for (int cc = 0; cc < 2; cc++) {
            int b = we_ni * 8 + 2 * (lane & 3) + cc;
            float hnew = hnew2[cc];
            float g = 0.5f * hnew * (1.0f + erff(hnew * 0.70710678118f));
            out[((size_t)b * TT + t) * (size_t)(2 * HH) + (size_t)dir * HH + kg] = g;
        }
    }
}

// ---------------- launcher ----------------
extern "C" void kernel_launch(void* const* d_in, const int* in_sizes, int n_in,
                              void* d_out, int out_size) {
    const float* x       = (const float*)d_in[0];
    const float* ln_g    = (const float*)d_in[1];
    const float* ln_b    = (const float*)d_in[2];
    const float* w_ih_f  = (const float*)d_in[3];
    const float* w_hh_f  = (const float*)d_in[4];
    const float* b_ih_f  = (const float*)d_in[5];
    const float* b_hh_f  = (const float*)d_in[6];
    const float* w_ih_b  = (const float*)d_in[7];
    const float* w_hh_b  = (const float*)d_in[8];
    const float* b_ih_b  = (const float*)d_in[9];
    const float* b_hh_b  = (const float*)d_in[10];
    float* out = (float*)d_out;

    static bool attr_done = false;
    if (!attr_done) {
        cudaFuncSetAttribute(gemm_kernel, cudaFuncAttributeMaxDynamicSharedMemorySize,
                             4 * GEMM_BUF_FLOATS * 4);
        cudaFuncSetAttribute(rec_kernel, cudaFuncAttributeMaxDynamicSharedMemorySize,
                             REC_SMEM_BYTES);
        attr_done = true;
    }

    prep_kernel<<<2048, 256>>>(w_ih_f, w_hh_f, w_ih_b, w_hh_b);
    ln_kernel<<<BATCH * TT, 128>>>(x, ln_g, ln_b);
    gemm_kernel<<<dim3(256, 12, 2), 256, 4 * GEMM_BUF_FLOATS * 4>>>(b_ih_f, b_ih_b);
    rec_kernel<<<dim3(NCTA_PER_DIR, 2), 256, REC_SMEM_BYTES>>>(b_hh_f, b_hh_b, out);
}